// round 2
// baseline (speedup 1.0000x reference)
#include <cuda_runtime.h>
#include <cuda_bf16.h>

#define D 128
#define MAX_N 50000
#define EDGES_PER_WARP 64

#define GEMM_ROWS 64          // M tile per block
#define LDS_W 132             // sW[k][o] padded row (words)
#define LDS_A 68              // sA[k][m] padded row (words)
#define GEMM_SMEM_BYTES ((128 * LDS_W + 128 * LDS_A) * 4)

// Scratch (static device globals: no allocation allowed)
__device__ float g_agg[(size_t)MAX_N * D];   // A_sparse @ input
__device__ float g_deg[MAX_N];               // rowsum of adj_val

// ---------------------------------------------------------------------------
// f32x2 helpers
// ---------------------------------------------------------------------------
__device__ __forceinline__ void ffma2(unsigned long long& d,
                                      unsigned long long a,
                                      unsigned long long b) {
    asm("fma.rn.f32x2 %0, %1, %2, %0;" : "+l"(d) : "l"(a), "l"(b));
}
__device__ __forceinline__ unsigned long long dup2(float x) {
    unsigned long long r;
    asm("mov.b64 %0, {%1, %1};" : "=l"(r) : "f"(x));
    return r;
}
__device__ __forceinline__ void unpack2(unsigned long long v, float& lo, float& hi) {
    asm("mov.b64 {%0, %1}, %2;" : "=f"(lo), "=f"(hi) : "l"(v));
}
__device__ __forceinline__ unsigned sptr(const void* p) {
    return (unsigned)__cvta_generic_to_shared(p);
}

// ---------------------------------------------------------------------------
// Kernel 1: COO scatter on the INPUT (algebraic rewrite):
//   g_agg[r] += val * input[c],   g_deg[r] += val
// One warp per 64-edge chunk; sorted rows -> register-run accumulation,
// plain stores for interior rows, atomics only at chunk boundaries.
// ---------------------------------------------------------------------------
__device__ __forceinline__ void flush_row(float* __restrict__ agg,
                                          float* __restrict__ deg,
                                          int curRow, int lane,
                                          const float4& acc, float degAcc,
                                          int firstRow, bool isFinal)
{
    if (curRow < 0) return;
    float* p = agg + (size_t)curRow * D + lane * 4;
    if (curRow == firstRow || isFinal) {
        atomicAdd(p + 0, acc.x);
        atomicAdd(p + 1, acc.y);
        atomicAdd(p + 2, acc.z);
        atomicAdd(p + 3, acc.w);
        if (lane == 0) atomicAdd(&deg[curRow], degAcc);
    } else {
        *reinterpret_cast<float4*>(p) = acc;
        if (lane == 0) deg[curRow] = degAcc;
    }
}

__global__ __launch_bounds__(256) void scatter_kernel(
    const int* __restrict__ adj_row,
    const int* __restrict__ adj_col,
    const float* __restrict__ adj_val,
    const float* __restrict__ input,
    float* __restrict__ agg,
    float* __restrict__ deg,
    int E)
{
    const int warpId = (blockIdx.x * blockDim.x + threadIdx.x) >> 5;
    const int lane = threadIdx.x & 31;
    const int base = warpId * EDGES_PER_WARP;
    if (base >= E) return;

    const int firstRow = adj_row[base];
    int curRow = -1;
    float4 acc = make_float4(0.f, 0.f, 0.f, 0.f);
    float degAcc = 0.f;

    for (int t = 0; t < EDGES_PER_WARP; t += 32) {
        const int e = base + t + lane;
        int r = -2, c = 0;
        float v = 0.f;
        if (e < E) { r = adj_row[e]; c = adj_col[e]; v = adj_val[e]; }

        #pragma unroll
        for (int j = 0; j < 32; ++j) {
            const int   rj = __shfl_sync(0xFFFFFFFFu, r, j);
            const int   cj = __shfl_sync(0xFFFFFFFFu, c, j);
            const float vj = __shfl_sync(0xFFFFFFFFu, v, j);
            if (rj < 0) break;   // trailing invalid edges (uniform)
            if (rj != curRow) {
                flush_row(agg, deg, curRow, lane, acc, degAcc, firstRow, false);
                curRow = rj;
                acc = make_float4(0.f, 0.f, 0.f, 0.f);
                degAcc = 0.f;
            }
            const float4 s = *reinterpret_cast<const float4*>(
                &input[(size_t)cj * D + lane * 4]);
            acc.x += vj * s.x;
            acc.y += vj * s.y;
            acc.z += vj * s.z;
            acc.w += vj * s.w;
            degAcc += vj;
        }
    }
    flush_row(agg, deg, curRow, lane, acc, degAcc, firstRow, true);
}

// ---------------------------------------------------------------------------
// Kernel 2: out[n][o] = tanh( sum_k agg[n][k] * W[o][k] + deg[n]*b[o] )
// 256 threads, 64x128 tile. Whole W^T + transposed A tile in smem.
// Micro-tile: 4 rows x 8 cols as 4x4 f32x2 accumulators (packed FFMA2).
// ---------------------------------------------------------------------------
__global__ __launch_bounds__(256, 2) void gemm_out_kernel(
    const float* __restrict__ agg,
    const float* __restrict__ W,
    const float* __restrict__ b,
    const float* __restrict__ deg,
    float* __restrict__ out,
    int N)
{
    extern __shared__ float smem[];
    float* sW = smem;                  // [128][LDS_W]  sW[k][o] = W[o][k]
    float* sA = smem + 128 * LDS_W;    // [128][LDS_A]  sA[k][m]

    const int tid = threadIdx.x;
    const int rowBase = blockIdx.x * GEMM_ROWS;

    // W transposed into shared
    #pragma unroll 4
    for (int idx = tid; idx < D * D; idx += 256) {
        int o = idx >> 7;
        int k = idx & 127;
        sW[k * LDS_W + o] = W[idx];
    }

    // A tile transposed into shared (zero-pad past N)
    #pragma unroll
    for (int i = 0; i < 8; ++i) {               // 2048 float4 / 256 threads
        int idx4 = tid + i * 256;
        int r  = idx4 >> 5;                      // 0..63
        int kk = (idx4 & 31) << 2;
        float4 v = make_float4(0.f, 0.f, 0.f, 0.f);
        int row = rowBase + r;
        if (row < N)
            v = *reinterpret_cast<const float4*>(&agg[(size_t)row * D + kk]);
        sA[(kk + 0) * LDS_A + r] = v.x;
        sA[(kk + 1) * LDS_A + r] = v.y;
        sA[(kk + 2) * LDS_A + r] = v.z;
        sA[(kk + 3) * LDS_A + r] = v.w;
    }
    __syncthreads();

    const int cg = tid & 15;    // cols cg*8 .. cg*8+7  (4 f32x2 pairs)
    const int rg = tid >> 4;    // rows rg*4 .. rg*4+3

    unsigned long long acc[4][4] = {};

    const unsigned aAddr0 = sptr(&sA[rg * 4]);
    const unsigned wAddr0 = sptr(&sW[cg * 8]);

    #pragma unroll 8
    for (int k = 0; k < D; ++k) {
        float4 a = *reinterpret_cast<const float4*>(
            (const char*)smem + ((size_t)(aAddr0 - sptr(smem)) + (size_t)k * (LDS_A * 4)));
        // (compiler folds this to a single LDS.128 with immediate offset)

        unsigned long long w01, w23, w45, w67;
        asm("ld.shared.v2.b64 {%0, %1}, [%2];"
            : "=l"(w01), "=l"(w23) : "r"(wAddr0 + (unsigned)(k * (LDS_W * 4))));
        asm("ld.shared.v2.b64 {%0, %1}, [%2];"
            : "=l"(w45), "=l"(w67) : "r"(wAddr0 + (unsigned)(k * (LDS_W * 4) + 16)));

        unsigned long long a0 = dup2(a.x);
        unsigned long long a1 = dup2(a.y);
        unsigned long long a2 = dup2(a.z);
        unsigned long long a3 = dup2(a.w);

        ffma2(acc[0][0], a0, w01); ffma2(acc[0][1], a0, w23);
        ffma2(acc[0][2], a0, w45); ffma2(acc[0][3], a0, w67);
        ffma2(acc[1][0], a1, w01); ffma2(acc[1][1], a1, w23);
        ffma2(acc[1][2], a1, w45); ffma2(acc[1][3], a1, w67);
        ffma2(acc[2][0], a2, w01); ffma2(acc[2][1], a2, w23);
        ffma2(acc[2][2], a2, w45); ffma2(acc[2][3], a2, w67);
        ffma2(acc[3][0], a3, w01); ffma2(acc[3][1], a3, w23);
        ffma2(acc[3][2], a3, w45); ffma2(acc[3][3], a3, w67);
    }

    // Epilogue: + deg*b, tanh, store
    float bv[8];
    #pragma unroll
    for (int j = 0; j < 8; ++j) bv[j] = b[cg * 8 + j];

    #pragma unroll
    for (int i = 0; i < 4; ++i) {
        int row = rowBase + rg * 4 + i;
        if (row >= N) continue;
        float dg = deg[row];
        float r0, r1, r2, r3, r4, r5, r6, r7;
        unpack2(acc[i][0], r0, r1);
        unpack2(acc[i][1], r2, r3);
        unpack2(acc[i][2], r4, r5);
        unpack2(acc[i][3], r6, r7);
        float4 o0, o1;
        o0.x = tanhf(r0 + dg * bv[0]);
        o0.y = tanhf(r1 + dg * bv[1]);
        o0.z = tanhf(r2 + dg * bv[2]);
        o0.w = tanhf(r3 + dg * bv[3]);
        o1.x = tanhf(r4 + dg * bv[4]);
        o1.y = tanhf(r5 + dg * bv[5]);
        o1.z = tanhf(r6 + dg * bv[6]);
        o1.w = tanhf(r7 + dg * bv[7]);
        float* p = out + (size_t)row * D + cg * 8;
        *reinterpret_cast<float4*>(p)     = o0;
        *reinterpret_cast<float4*>(p + 4) = o1;
    }
}

// ---------------------------------------------------------------------------
extern "C" void kernel_launch(void* const* d_in, const int* in_sizes, int n_in,
                              void* d_out, int out_size)
{
    const float* input   = (const float*)d_in[0];
    const float* W       = (const float*)d_in[1];
    const float* b       = (const float*)d_in[2];
    const int*   adj_row = (const int*)d_in[3];
    const int*   adj_col = (const int*)d_in[4];
    const float* adj_val = (const float*)d_in[5];
    float* out = (float*)d_out;

    const int N = in_sizes[0] / D;
    const int E = in_sizes[3];

    float *aggPtr = nullptr, *degPtr = nullptr;
    cudaGetSymbolAddress((void**)&aggPtr, g_agg);
    cudaGetSymbolAddress((void**)&degPtr, g_deg);

    cudaMemsetAsync(aggPtr, 0, (size_t)N * D * sizeof(float));
    cudaMemsetAsync(degPtr, 0, (size_t)N * sizeof(float));

    // Scatter: g_agg = A_sparse @ input, g_deg = rowsum(adj_val)
    const int nWarps = (E + EDGES_PER_WARP - 1) / EDGES_PER_WARP;
    const int scatterBlocks = (nWarps * 32 + 255) / 256;
    scatter_kernel<<<scatterBlocks, 256>>>(adj_row, adj_col, adj_val,
                                           input, aggPtr, degPtr, E);

    // GEMM + bias + tanh fused, writes out directly
    cudaFuncSetAttribute(gemm_out_kernel,
                         cudaFuncAttributeMaxDynamicSharedMemorySize,
                         GEMM_SMEM_BYTES);
    const int gemmBlocks = (N + GEMM_ROWS - 1) / GEMM_ROWS;
    gemm_out_kernel<<<gemmBlocks, 256, GEMM_SMEM_BYTES>>>(
        aggPtr, W, b, degPtr, out, N);
}

// round 4
// speedup vs baseline: 2.8742x; 2.8742x over previous
#include <cuda_runtime.h>
#include <cuda_bf16.h>
#include <cstdint>

#define D 128
#define MAX_N 50000
#define EDGES_PER_WARP 64

// ===========================================================================
// Static scratch (no allocations allowed)
// ===========================================================================
__device__ float g_agg[(size_t)MAX_N * D];   // A_sparse @ input
__device__ float g_deg[MAX_N];               // rowsum of adj_val

// ===========================================================================
// Kernel 1: COO scatter on the input (algebraic rewrite):
//   g_agg[r] += val * input[c],   g_deg[r] += val
// Sorted rows -> register-run accumulation; plain stores for interior rows,
// atomics only at chunk boundaries.
// ===========================================================================
__device__ __forceinline__ void flush_row(float* __restrict__ agg,
                                          float* __restrict__ deg,
                                          int curRow, int lane,
                                          const float4& acc, float degAcc,
                                          int firstRow, bool isFinal)
{
    if (curRow < 0) return;
    float* p = agg + (size_t)curRow * D + lane * 4;
    if (curRow == firstRow || isFinal) {
        atomicAdd(p + 0, acc.x);
        atomicAdd(p + 1, acc.y);
        atomicAdd(p + 2, acc.z);
        atomicAdd(p + 3, acc.w);
        if (lane == 0) atomicAdd(&deg[curRow], degAcc);
    } else {
        *reinterpret_cast<float4*>(p) = acc;
        if (lane == 0) deg[curRow] = degAcc;
    }
}

__global__ __launch_bounds__(256) void scatter_kernel(
    const int* __restrict__ adj_row,
    const int* __restrict__ adj_col,
    const float* __restrict__ adj_val,
    const float* __restrict__ input,
    float* __restrict__ agg,
    float* __restrict__ deg,
    int E)
{
    const int warpId = (blockIdx.x * blockDim.x + threadIdx.x) >> 5;
    const int lane = threadIdx.x & 31;
    const int base = warpId * EDGES_PER_WARP;
    if (base >= E) return;

    const int firstRow = adj_row[base];
    int curRow = -1;
    float4 acc = make_float4(0.f, 0.f, 0.f, 0.f);
    float degAcc = 0.f;

    for (int t = 0; t < EDGES_PER_WARP; t += 32) {
        const int e = base + t + lane;
        int r = -2, c = 0;
        float v = 0.f;
        if (e < E) { r = adj_row[e]; c = adj_col[e]; v = adj_val[e]; }

        #pragma unroll
        for (int j = 0; j < 32; ++j) {
            const int   rj = __shfl_sync(0xFFFFFFFFu, r, j);
            const int   cj = __shfl_sync(0xFFFFFFFFu, c, j);
            const float vj = __shfl_sync(0xFFFFFFFFu, v, j);
            if (rj < 0) break;
            if (rj != curRow) {
                flush_row(agg, deg, curRow, lane, acc, degAcc, firstRow, false);
                curRow = rj;
                acc = make_float4(0.f, 0.f, 0.f, 0.f);
                degAcc = 0.f;
            }
            const float4 s = *reinterpret_cast<const float4*>(
                &input[(size_t)cj * D + lane * 4]);
            acc.x += vj * s.x;
            acc.y += vj * s.y;
            acc.z += vj * s.z;
            acc.w += vj * s.w;
            degAcc += vj;
        }
    }
    flush_row(agg, deg, curRow, lane, acc, degAcc, firstRow, true);
}

// ===========================================================================
// mma.sync / ldmatrix helpers (sm_80 baseline features; no 'a'-arch needed)
// ===========================================================================
__device__ __forceinline__ void ldmx4(uint32_t& r0, uint32_t& r1,
                                      uint32_t& r2, uint32_t& r3,
                                      uint32_t saddr)
{
    asm volatile("ldmatrix.sync.aligned.m8n8.x4.shared.b16 {%0,%1,%2,%3}, [%4];"
                 : "=r"(r0), "=r"(r1), "=r"(r2), "=r"(r3) : "r"(saddr));
}

__device__ __forceinline__ void mma_bf16(float& c0, float& c1, float& c2, float& c3,
                                         uint32_t a0, uint32_t a1, uint32_t a2, uint32_t a3,
                                         uint32_t b0, uint32_t b1)
{
    asm volatile(
        "mma.sync.aligned.m16n8k16.row.col.f32.bf16.bf16.f32 "
        "{%0,%1,%2,%3}, {%4,%5,%6,%7}, {%8,%9}, {%0,%1,%2,%3};"
        : "+f"(c0), "+f"(c1), "+f"(c2), "+f"(c3)
        : "r"(a0), "r"(a1), "r"(a2), "r"(a3), "r"(b0), "r"(b1));
}

__device__ __forceinline__ uint32_t smem_u32(const void* p) {
    return (uint32_t)__cvta_generic_to_shared(p);
}

// ===========================================================================
// Kernel 2: bf16-split tensor-core GEMM + fused epilogue
//   out[n][o] = tanh( sum_k agg[n][k] * W[o][k] + deg[n]*b[o] )
// CTA: 128(M) x 128(N), K=128 fully resident.
// 8 warps: warp (wm=wid&3, wn=wid>>2) owns 32(M) x 64(N).
// Split X = Xh + Xl (bf16): D = AhBh + AlBh + AhBl, fp32 accum.
// ===========================================================================
#define LDT 136                       // padded bf16 row stride (272 B)
#define T_BYTES (128 * LDT * 2)       // 34816 B per tile
#define SM_BV   0                     // 128 floats of b
#define SM_AH   1024
#define SM_AL   (SM_AH + T_BYTES)
#define SM_BH   (SM_AL + T_BYTES)
#define SM_BL   (SM_BH + T_BYTES)
#define GEMM_SMEM_TOTAL (SM_BL + T_BYTES)   // 140288 B

__global__ __launch_bounds__(256, 1) void gemm_mma_kernel(
    const float* __restrict__ agg,
    const float* __restrict__ W,
    const float* __restrict__ b,
    const float* __restrict__ deg,
    float* __restrict__ out,
    int N)
{
    extern __shared__ char smem[];
    float* sb = reinterpret_cast<float*>(smem + SM_BV);

    const int tid  = threadIdx.x;
    const int wid  = tid >> 5;
    const int lane = tid & 31;
    const int rowBase = blockIdx.x * 128;

    if (tid < 128) sb[tid] = b[tid];

    // ---- Fill smem: split-convert agg tile (A) and W (B) ----
    #pragma unroll 4
    for (int i = tid; i < 4096; i += 256) {
        int r  = i >> 5;              // 0..127
        int k4 = (i & 31) << 2;       // 0,4,...,124
        int grow = rowBase + r;
        float4 v = make_float4(0.f, 0.f, 0.f, 0.f);
        if (grow < N)
            v = *reinterpret_cast<const float4*>(&agg[(size_t)grow * D + k4]);

        __nv_bfloat162 h0, h1, l0, l1;
        h0.x = __float2bfloat16(v.x); h0.y = __float2bfloat16(v.y);
        h1.x = __float2bfloat16(v.z); h1.y = __float2bfloat16(v.w);
        l0.x = __float2bfloat16(v.x - __bfloat162float(h0.x));
        l0.y = __float2bfloat16(v.y - __bfloat162float(h0.y));
        l1.x = __float2bfloat16(v.z - __bfloat162float(h1.x));
        l1.y = __float2bfloat16(v.w - __bfloat162float(h1.y));

        uint32_t off = (uint32_t)(r * LDT + k4) * 2;  // 8B aligned
        *reinterpret_cast<uint2*>(smem + SM_AH + off) =
            make_uint2(*reinterpret_cast<uint32_t*>(&h0), *reinterpret_cast<uint32_t*>(&h1));
        *reinterpret_cast<uint2*>(smem + SM_AL + off) =
            make_uint2(*reinterpret_cast<uint32_t*>(&l0), *reinterpret_cast<uint32_t*>(&l1));
    }

    #pragma unroll 4
    for (int i = tid; i < 4096; i += 256) {
        int r  = i >> 5;
        int k4 = (i & 31) << 2;
        float4 v = *reinterpret_cast<const float4*>(&W[(size_t)r * D + k4]);

        __nv_bfloat162 h0, h1, l0, l1;
        h0.x = __float2bfloat16(v.x); h0.y = __float2bfloat16(v.y);
        h1.x = __float2bfloat16(v.z); h1.y = __float2bfloat16(v.w);
        l0.x = __float2bfloat16(v.x - __bfloat162float(h0.x));
        l0.y = __float2bfloat16(v.y - __bfloat162float(h0.y));
        l1.x = __float2bfloat16(v.z - __bfloat162float(h1.x));
        l1.y = __float2bfloat16(v.w - __bfloat162float(h1.y));

        uint32_t off = (uint32_t)(r * LDT + k4) * 2;
        *reinterpret_cast<uint2*>(smem + SM_BH + off) =
            make_uint2(*reinterpret_cast<uint32_t*>(&h0), *reinterpret_cast<uint32_t*>(&h1));
        *reinterpret_cast<uint2*>(smem + SM_BL + off) =
            make_uint2(*reinterpret_cast<uint32_t*>(&l0), *reinterpret_cast<uint32_t*>(&l1));
    }
    __syncthreads();

    // ---- Warp-tile MMA ----
    const int wm = wid & 3;     // M group: rows wm*32..+31
    const int wn = wid >> 2;    // N group: cols wn*64..+63

    float acc[2][8][4];
    #pragma unroll
    for (int mi = 0; mi < 2; ++mi)
        #pragma unroll
        for (int ni = 0; ni < 8; ++ni)
            #pragma unroll
            for (int q = 0; q < 4; ++q)
                acc[mi][ni][q] = 0.f;

    // ldmatrix addressing: row = (lane & 15), k-half = (lane >> 4) * 8
    const int lrow = lane & 15;
    const int lkof = (lane >> 4) << 3;

    const uint32_t base_ah = smem_u32(smem + SM_AH);
    const uint32_t base_al = smem_u32(smem + SM_AL);
    const uint32_t base_bh = smem_u32(smem + SM_BH);
    const uint32_t base_bl = smem_u32(smem + SM_BL);

    #pragma unroll
    for (int ks = 0; ks < 8; ++ks) {
        const uint32_t kb = (uint32_t)(ks * 16 + lkof) * 2;

        uint32_t ah[2][4], al[2][4];
        #pragma unroll
        for (int mi = 0; mi < 2; ++mi) {
            uint32_t ra = (uint32_t)((wm * 32 + mi * 16 + lrow) * LDT) * 2 + kb;
            ldmx4(ah[mi][0], ah[mi][1], ah[mi][2], ah[mi][3], base_ah + ra);
            ldmx4(al[mi][0], al[mi][1], al[mi][2], al[mi][3], base_al + ra);
        }

        uint32_t bh[4][4], bl[4][4];
        #pragma unroll
        for (int nb = 0; nb < 4; ++nb) {
            uint32_t rb = (uint32_t)((wn * 64 + nb * 16 + lrow) * LDT) * 2 + kb;
            ldmx4(bh[nb][0], bh[nb][1], bh[nb][2], bh[nb][3], base_bh + rb);
            ldmx4(bl[nb][0], bl[nb][1], bl[nb][2], bl[nb][3], base_bl + rb);
        }

        #pragma unroll
        for (int mi = 0; mi < 2; ++mi) {
            #pragma unroll
            for (int nb = 0; nb < 4; ++nb) {
                // n-frag 2*nb   : regs {0,2};  n-frag 2*nb+1 : regs {1,3}
                mma_bf16(acc[mi][nb*2][0], acc[mi][nb*2][1], acc[mi][nb*2][2], acc[mi][nb*2][3],
                         ah[mi][0], ah[mi][1], ah[mi][2], ah[mi][3], bh[nb][0], bh[nb][2]);
                mma_bf16(acc[mi][nb*2+1][0], acc[mi][nb*2+1][1], acc[mi][nb*2+1][2], acc[mi][nb*2+1][3],
                         ah[mi][0], ah[mi][1], ah[mi][2], ah[mi][3], bh[nb][1], bh[nb][3]);
                mma_bf16(acc[mi][nb*2][0], acc[mi][nb*2][1], acc[mi][nb*2][2], acc[mi][nb*2][3],
                         al[mi][0], al[mi][1], al[mi][2], al[mi][3], bh[nb][0], bh[nb][2]);
                mma_bf16(acc[mi][nb*2+1][0], acc[mi][nb*2+1][1], acc[mi][nb*2+1][2], acc[mi][nb*2+1][3],
                         al[mi][0], al[mi][1], al[mi][2], al[mi][3], bh[nb][1], bh[nb][3]);
                mma_bf16(acc[mi][nb*2][0], acc[mi][nb*2][1], acc[mi][nb*2][2], acc[mi][nb*2][3],
                         ah[mi][0], ah[mi][1], ah[mi][2], ah[mi][3], bl[nb][0], bl[nb][2]);
                mma_bf16(acc[mi][nb*2+1][0], acc[mi][nb*2+1][1], acc[mi][nb*2+1][2], acc[mi][nb*2+1][3],
                         ah[mi][0], ah[mi][1], ah[mi][2], ah[mi][3], bl[nb][1], bl[nb][3]);
            }
        }
    }

    // ---- Epilogue: acc + deg*b, tanh, store ----
    const int qrow = lane >> 2;          // 0..7
    const int qcol = (lane & 3) << 1;    // 0,2,4,6

    #pragma unroll
    for (int mi = 0; mi < 2; ++mi) {
        const int r0 = rowBase + wm * 32 + mi * 16 + qrow;
        const int r1 = r0 + 8;
        const float d0 = (r0 < N) ? deg[r0] : 0.f;
        const float d1 = (r1 < N) ? deg[r1] : 0.f;
        #pragma unroll
        for (int ni = 0; ni < 8; ++ni) {
            const int c = wn * 64 + ni * 8 + qcol;
            const float b0v = sb[c], b1v = sb[c + 1];
            if (r0 < N) {
                float2 o;
                o.x = tanhf(acc[mi][ni][0] + d0 * b0v);
                o.y = tanhf(acc[mi][ni][1] + d0 * b1v);
                *reinterpret_cast<float2*>(&out[(size_t)r0 * D + c]) = o;
            }
            if (r1 < N) {
                float2 o;
                o.x = tanhf(acc[mi][ni][2] + d1 * b0v);
                o.y = tanhf(acc[mi][ni][3] + d1 * b1v);
                *reinterpret_cast<float2*>(&out[(size_t)r1 * D + c]) = o;
            }
        }
    }
}

// ===========================================================================
extern "C" void kernel_launch(void* const* d_in, const int* in_sizes, int n_in,
                              void* d_out, int out_size)
{
    const float* input   = (const float*)d_in[0];
    const float* W       = (const float*)d_in[1];
    const float* b       = (const float*)d_in[2];
    const int*   adj_row = (const int*)d_in[3];
    const int*   adj_col = (const int*)d_in[4];
    const float* adj_val = (const float*)d_in[5];
    float* out = (float*)d_out;

    const int N = in_sizes[0] / D;
    const int E = in_sizes[3];

    float *aggPtr = nullptr, *degPtr = nullptr;
    cudaGetSymbolAddress((void**)&aggPtr, g_agg);
    cudaGetSymbolAddress((void**)&degPtr, g_deg);

    cudaMemsetAsync(aggPtr, 0, (size_t)N * D * sizeof(float));
    cudaMemsetAsync(degPtr, 0, (size_t)N * sizeof(float));

    // Scatter: g_agg = A_sparse @ input, g_deg = rowsum(adj_val)
    const int nWarps = (E + EDGES_PER_WARP - 1) / EDGES_PER_WARP;
    const int scatterBlocks = (nWarps * 32 + 255) / 256;
    scatter_kernel<<<scatterBlocks, 256>>>(adj_row, adj_col, adj_val,
                                           input, aggPtr, degPtr, E);

    // Tensor-core GEMM + fused bias/tanh epilogue
    cudaFuncSetAttribute(gemm_mma_kernel,
                         cudaFuncAttributeMaxDynamicSharedMemorySize,
                         GEMM_SMEM_TOTAL);
    const int gemmBlocks = (N + 127) / 128;
    gemm_mma_kernel<<<gemmBlocks, 256, GEMM_SMEM_TOTAL>>>(
        aggPtr, W, b, degPtr, out, N);
}

// round 5
// speedup vs baseline: 3.8790x; 1.3496x over previous
#include <cuda_runtime.h>
#include <cuda_fp16.h>
#include <cstdint>

#define D 128
#define MAX_N 50000
#define MAX_N_PAD 50176          // padded so GEMM tiles can over-read safely
#define EDGES_PER_WARP 64

// ===========================================================================
// Static scratch (no allocations allowed). Zero-initialized by CUDA runtime.
// ===========================================================================
__device__ __align__(256) __half g_in_h[(size_t)MAX_N * D];       // fp16 input
__device__ __align__(256) __half g_W_h[D * D];                    // fp16 W
__device__ __align__(256) __half g_agg_h[(size_t)MAX_N_PAD * D];  // fp16 agg
__device__ float g_deg[MAX_N];                                    // rowsum(adj_val)

// ===========================================================================
// Kernel 0: convert input and W to fp16
// ===========================================================================
__global__ __launch_bounds__(256) void convert_kernel(
    const float* __restrict__ input,
    const float* __restrict__ W,
    __half* __restrict__ in_h,
    __half* __restrict__ W_h,
    int nIn4, int nW4)
{
    const int i = blockIdx.x * blockDim.x + threadIdx.x;
    if (i >= nIn4 + nW4) return;
    float4 v;
    if (i < nIn4) v = reinterpret_cast<const float4*>(input)[i];
    else          v = reinterpret_cast<const float4*>(W)[i - nIn4];
    __half2 h0 = __floats2half2_rn(v.x, v.y);
    __half2 h1 = __floats2half2_rn(v.z, v.w);
    uint2 u = make_uint2(*reinterpret_cast<uint32_t*>(&h0),
                         *reinterpret_cast<uint32_t*>(&h1));
    if (i < nIn4) reinterpret_cast<uint2*>(in_h)[i] = u;
    else          reinterpret_cast<uint2*>(W_h)[i - nIn4] = u;
}

// ===========================================================================
// Kernel 1: COO scatter on fp16 input, fp32 register accumulation:
//   g_agg_h[r] += val * in_h[c]  (fp16 store),  g_deg[r] += val
// Sorted rows -> register-run accumulation; plain 8B stores for interior
// rows, f16x2 atomics only at chunk boundaries.
// ===========================================================================
__device__ __forceinline__ void flush_row(__half* __restrict__ agg,
                                          float* __restrict__ deg,
                                          int curRow, int lane,
                                          const float4& acc, float degAcc,
                                          int firstRow, bool isFinal)
{
    if (curRow < 0) return;
    __half2 h0 = __floats2half2_rn(acc.x, acc.y);
    __half2 h1 = __floats2half2_rn(acc.z, acc.w);
    __half2* p = reinterpret_cast<__half2*>(agg + (size_t)curRow * D + lane * 4);
    if (curRow == firstRow || isFinal) {
        atomicAdd(p + 0, h0);
        atomicAdd(p + 1, h1);
        if (lane == 0) atomicAdd(&deg[curRow], degAcc);
    } else {
        uint2 u = make_uint2(*reinterpret_cast<uint32_t*>(&h0),
                             *reinterpret_cast<uint32_t*>(&h1));
        *reinterpret_cast<uint2*>(p) = u;
        if (lane == 0) deg[curRow] = degAcc;
    }
}

__global__ __launch_bounds__(256) void scatter_kernel(
    const int* __restrict__ adj_row,
    const int* __restrict__ adj_col,
    const float* __restrict__ adj_val,
    const __half* __restrict__ in_h,
    __half* __restrict__ agg,
    float* __restrict__ deg,
    int E)
{
    const int warpId = (blockIdx.x * blockDim.x + threadIdx.x) >> 5;
    const int lane = threadIdx.x & 31;
    const int base = warpId * EDGES_PER_WARP;
    if (base >= E) return;

    const int firstRow = adj_row[base];
    int curRow = -1;
    float4 acc = make_float4(0.f, 0.f, 0.f, 0.f);
    float degAcc = 0.f;

    for (int t = 0; t < EDGES_PER_WARP; t += 32) {
        const int e = base + t + lane;
        int r = -2, c = 0;
        float v = 0.f;
        if (e < E) { r = adj_row[e]; c = adj_col[e]; v = adj_val[e]; }

        #pragma unroll
        for (int j = 0; j < 32; ++j) {
            const int   rj = __shfl_sync(0xFFFFFFFFu, r, j);
            const int   cj = __shfl_sync(0xFFFFFFFFu, c, j);
            const float vj = __shfl_sync(0xFFFFFFFFu, v, j);
            if (rj < 0) break;
            if (rj != curRow) {
                flush_row(agg, deg, curRow, lane, acc, degAcc, firstRow, false);
                curRow = rj;
                acc = make_float4(0.f, 0.f, 0.f, 0.f);
                degAcc = 0.f;
            }
            const uint2 sv = *reinterpret_cast<const uint2*>(
                in_h + (size_t)cj * D + lane * 4);
            const float2 f0 = __half22float2(*reinterpret_cast<const __half2*>(&sv.x));
            const float2 f1 = __half22float2(*reinterpret_cast<const __half2*>(&sv.y));
            acc.x += vj * f0.x;
            acc.y += vj * f0.y;
            acc.z += vj * f1.x;
            acc.w += vj * f1.y;
            degAcc += vj;
        }
    }
    flush_row(agg, deg, curRow, lane, acc, degAcc, firstRow, true);
}

// ===========================================================================
// mma.sync / ldmatrix / cp.async helpers (sm_80 baseline features)
// ===========================================================================
__device__ __forceinline__ void ldmx4(uint32_t& r0, uint32_t& r1,
                                      uint32_t& r2, uint32_t& r3,
                                      uint32_t saddr)
{
    asm volatile("ldmatrix.sync.aligned.m8n8.x4.shared.b16 {%0,%1,%2,%3}, [%4];"
                 : "=r"(r0), "=r"(r1), "=r"(r2), "=r"(r3) : "r"(saddr));
}

__device__ __forceinline__ void mma_f16(float& c0, float& c1, float& c2, float& c3,
                                        uint32_t a0, uint32_t a1, uint32_t a2, uint32_t a3,
                                        uint32_t b0, uint32_t b1)
{
    asm volatile(
        "mma.sync.aligned.m16n8k16.row.col.f32.f16.f16.f32 "
        "{%0,%1,%2,%3}, {%4,%5,%6,%7}, {%8,%9}, {%0,%1,%2,%3};"
        : "+f"(c0), "+f"(c1), "+f"(c2), "+f"(c3)
        : "r"(a0), "r"(a1), "r"(a2), "r"(a3), "r"(b0), "r"(b1));
}

__device__ __forceinline__ uint32_t smem_u32(const void* p) {
    return (uint32_t)__cvta_generic_to_shared(p);
}
__device__ __forceinline__ void cp16(uint32_t dst, const void* src) {
    asm volatile("cp.async.cg.shared.global [%0], [%1], 16;" :: "r"(dst), "l"(src));
}
__device__ __forceinline__ void cp_commit_wait0() {
    asm volatile("cp.async.commit_group;");
    asm volatile("cp.async.wait_group 0;");
}

// ===========================================================================
// Kernel 2: fp16 tensor-core GEMM + fused epilogue
//   out[n][o] = tanh( sum_k agg[n][k] * W[o][k] + deg[n]*b[o] )
// CTA: 128(M) x 128(N), K=128 fully resident. 8 warps, warp tile 32M x 64N.
// Operands already fp16 in gmem -> pure cp.async fill, single MMA term.
// ===========================================================================
#define LDH 136                        // fp16 row stride (272 B, LDSM conflict-free)
#define TILE_BYTES_H (128 * LDH * 2)   // 34816 B
#define SM_BV 0
#define SM_A  1024
#define SM_B  (SM_A + TILE_BYTES_H)
#define GEMM_SMEM_TOTAL (SM_B + TILE_BYTES_H)   // 70656 B

__global__ __launch_bounds__(256, 2) void gemm_mma_kernel(
    const __half* __restrict__ agg,
    const __half* __restrict__ W_h,
    const float* __restrict__ b,
    const float* __restrict__ deg,
    float* __restrict__ out,
    int N)
{
    extern __shared__ char smem[];
    float* sb = reinterpret_cast<float*>(smem + SM_BV);

    const int tid  = threadIdx.x;
    const int wid  = tid >> 5;
    const int lane = tid & 31;
    const int rowBase = blockIdx.x * 128;

    if (tid < 128) sb[tid] = b[tid];

    // ---- Fill A (agg rows) and B (W) via cp.async, 16B chunks ----
    const uint32_t sA = smem_u32(smem + SM_A);
    const uint32_t sB = smem_u32(smem + SM_B);
    #pragma unroll
    for (int it = 0; it < 8; ++it) {
        const int i = tid + it * 256;     // 0..2047
        const int r = i >> 4;             // 16 chunks per row
        const int c = i & 15;
        cp16(sA + r * (LDH * 2) + c * 16,
             agg + (size_t)(rowBase + r) * D + c * 8);   // padded array: safe over-read
        cp16(sB + r * (LDH * 2) + c * 16,
             W_h + (size_t)r * D + c * 8);
    }
    cp_commit_wait0();
    __syncthreads();

    // ---- Warp-tile MMA (single fp16 term, fp32 accum) ----
    const int wm = wid & 3;     // rows wm*32..+31
    const int wn = wid >> 2;    // cols wn*64..+63

    float acc[2][8][4];
    #pragma unroll
    for (int mi = 0; mi < 2; ++mi)
        #pragma unroll
        for (int ni = 0; ni < 8; ++ni)
            #pragma unroll
            for (int q = 0; q < 4; ++q)
                acc[mi][ni][q] = 0.f;

    const int lrow = lane & 15;
    const int lkof = (lane >> 4) << 3;

    #pragma unroll
    for (int ks = 0; ks < 8; ++ks) {
        const uint32_t kb = (uint32_t)(ks * 16 + lkof) * 2;

        uint32_t a[2][4];
        #pragma unroll
        for (int mi = 0; mi < 2; ++mi) {
            uint32_t ra = (uint32_t)((wm * 32 + mi * 16 + lrow) * LDH) * 2 + kb;
            ldmx4(a[mi][0], a[mi][1], a[mi][2], a[mi][3], sA + ra);
        }
        uint32_t bf[4][4];
        #pragma unroll
        for (int nb = 0; nb < 4; ++nb) {
            uint32_t rb = (uint32_t)((wn * 64 + nb * 16 + lrow) * LDH) * 2 + kb;
            ldmx4(bf[nb][0], bf[nb][1], bf[nb][2], bf[nb][3], sB + rb);
        }

        #pragma unroll
        for (int mi = 0; mi < 2; ++mi) {
            #pragma unroll
            for (int nb = 0; nb < 4; ++nb) {
                mma_f16(acc[mi][nb*2][0], acc[mi][nb*2][1], acc[mi][nb*2][2], acc[mi][nb*2][3],
                        a[mi][0], a[mi][1], a[mi][2], a[mi][3], bf[nb][0], bf[nb][2]);
                mma_f16(acc[mi][nb*2+1][0], acc[mi][nb*2+1][1], acc[mi][nb*2+1][2], acc[mi][nb*2+1][3],
                        a[mi][0], a[mi][1], a[mi][2], a[mi][3], bf[nb][1], bf[nb][3]);
            }
        }
    }

    // ---- Epilogue: acc + deg*b, tanh, store ----
    const int qrow = lane >> 2;
    const int qcol = (lane & 3) << 1;

    #pragma unroll
    for (int mi = 0; mi < 2; ++mi) {
        const int r0 = rowBase + wm * 32 + mi * 16 + qrow;
        const int r1 = r0 + 8;
        const float d0 = (r0 < N) ? deg[r0] : 0.f;
        const float d1 = (r1 < N) ? deg[r1] : 0.f;
        #pragma unroll
        for (int ni = 0; ni < 8; ++ni) {
            const int c = wn * 64 + ni * 8 + qcol;
            const float b0v = sb[c], b1v = sb[c + 1];
            if (r0 < N) {
                float2 o;
                o.x = tanhf(acc[mi][ni][0] + d0 * b0v);
                o.y = tanhf(acc[mi][ni][1] + d0 * b1v);
                *reinterpret_cast<float2*>(&out[(size_t)r0 * D + c]) = o;
            }
            if (r1 < N) {
                float2 o;
                o.x = tanhf(acc[mi][ni][2] + d1 * b0v);
                o.y = tanhf(acc[mi][ni][3] + d1 * b1v);
                *reinterpret_cast<float2*>(&out[(size_t)r1 * D + c]) = o;
            }
        }
    }
}

// ===========================================================================
extern "C" void kernel_launch(void* const* d_in, const int* in_sizes, int n_in,
                              void* d_out, int out_size)
{
    const float* input   = (const float*)d_in[0];
    const float* W       = (const float*)d_in[1];
    const float* b       = (const float*)d_in[2];
    const int*   adj_row = (const int*)d_in[3];
    const int*   adj_col = (const int*)d_in[4];
    const float* adj_val = (const float*)d_in[5];
    float* out = (float*)d_out;

    const int N = in_sizes[0] / D;
    const int E = in_sizes[3];

    __half *inhPtr = nullptr, *whPtr = nullptr, *agghPtr = nullptr;
    float *degPtr = nullptr;
    cudaGetSymbolAddress((void**)&inhPtr, g_in_h);
    cudaGetSymbolAddress((void**)&whPtr, g_W_h);
    cudaGetSymbolAddress((void**)&agghPtr, g_agg_h);
    cudaGetSymbolAddress((void**)&degPtr, g_deg);

    // Convert input and W to fp16
    const int nIn4 = N * D / 4;
    const int nW4  = D * D / 4;
    convert_kernel<<<(nIn4 + nW4 + 255) / 256, 256>>>(
        input, W, inhPtr, whPtr, nIn4, nW4);

    // Zero agg (fp16) and deg
    cudaMemsetAsync(agghPtr, 0, (size_t)N * D * sizeof(__half));
    cudaMemsetAsync(degPtr, 0, (size_t)N * sizeof(float));

    // Scatter: g_agg_h = A_sparse @ input (fp16), g_deg = rowsum(adj_val)
    const int nWarps = (E + EDGES_PER_WARP - 1) / EDGES_PER_WARP;
    const int scatterBlocks = (nWarps * 32 + 255) / 256;
    scatter_kernel<<<scatterBlocks, 256>>>(adj_row, adj_col, adj_val,
                                           inhPtr, agghPtr, degPtr, E);

    // Tensor-core GEMM + fused bias/tanh epilogue
    cudaFuncSetAttribute(gemm_mma_kernel,
                         cudaFuncAttributeMaxDynamicSharedMemorySize,
                         GEMM_SMEM_TOTAL);
    const int gemmBlocks = (N + 127) / 128;
    gemm_mma_kernel<<<gemmBlocks, 256, GEMM_SMEM_TOTAL>>>(
        agghPtr, whPtr, b, degPtr, out, N);
}

// round 6
// speedup vs baseline: 4.2669x; 1.1000x over previous
#include <cuda_runtime.h>
#include <cuda_fp16.h>
#include <cstdint>

#define D 128
#define MAX_N 50000
#define MAX_N_PAD 50176          // padded: GEMM tiles may over-read safely
#define EDGES_PER_WARP 64

// ===========================================================================
// Static scratch (no allocations allowed)
// ===========================================================================
__device__ __align__(256) __half g_in_h[(size_t)MAX_N * D];       // fp16 input
__device__ __align__(256) __half g_W_h[D * D];                    // fp16 W
__device__ __align__(256) __half g_agg_h[(size_t)MAX_N_PAD * D];  // fp16 agg
__device__ __align__(256) float g_deg[MAX_N];                     // rowsum(adj_val)

// ===========================================================================
// Kernel 0: fused prep — convert input/W to fp16 AND zero agg/deg.
// Work items partitioned by index range; 16-32B per item.
// ===========================================================================
__global__ __launch_bounds__(256) void prep_kernel(
    const float* __restrict__ input,
    const float* __restrict__ W,
    __half* __restrict__ in_h,
    __half* __restrict__ W_h,
    __half* __restrict__ agg,
    float* __restrict__ deg,
    int nInPairs, int nWPairs, int nZero16, int nDeg4)
{
    const int i = blockIdx.x * blockDim.x + threadIdx.x;

    if (i < nInPairs) {
        // convert 8 floats of input -> 8 halves (one uint4 store)
        const float4 v0 = reinterpret_cast<const float4*>(input)[i * 2];
        const float4 v1 = reinterpret_cast<const float4*>(input)[i * 2 + 1];
        __half2 h0 = __floats2half2_rn(v0.x, v0.y);
        __half2 h1 = __floats2half2_rn(v0.z, v0.w);
        __half2 h2 = __floats2half2_rn(v1.x, v1.y);
        __half2 h3 = __floats2half2_rn(v1.z, v1.w);
        uint4 u;
        u.x = *reinterpret_cast<uint32_t*>(&h0);
        u.y = *reinterpret_cast<uint32_t*>(&h1);
        u.z = *reinterpret_cast<uint32_t*>(&h2);
        u.w = *reinterpret_cast<uint32_t*>(&h3);
        reinterpret_cast<uint4*>(in_h)[i] = u;
        return;
    }
    int j = i - nInPairs;
    if (j < nWPairs) {
        const float4 v0 = reinterpret_cast<const float4*>(W)[j * 2];
        const float4 v1 = reinterpret_cast<const float4*>(W)[j * 2 + 1];
        __half2 h0 = __floats2half2_rn(v0.x, v0.y);
        __half2 h1 = __floats2half2_rn(v0.z, v0.w);
        __half2 h2 = __floats2half2_rn(v1.x, v1.y);
        __half2 h3 = __floats2half2_rn(v1.z, v1.w);
        uint4 u;
        u.x = *reinterpret_cast<uint32_t*>(&h0);
        u.y = *reinterpret_cast<uint32_t*>(&h1);
        u.z = *reinterpret_cast<uint32_t*>(&h2);
        u.w = *reinterpret_cast<uint32_t*>(&h3);
        reinterpret_cast<uint4*>(W_h)[j] = u;
        return;
    }
    j -= nWPairs;
    if (j < nZero16) {
        reinterpret_cast<uint4*>(agg)[j] = make_uint4(0, 0, 0, 0);
        return;
    }
    j -= nZero16;
    if (j < nDeg4)
        reinterpret_cast<uint4*>(deg)[j] = make_uint4(0, 0, 0, 0);
}

// ===========================================================================
// Kernel 1: COO scatter on fp16 input, fp32 register accumulation:
//   g_agg_h[r] += val * in_h[c]  (fp16 store),  g_deg[r] += val
// ===========================================================================
__device__ __forceinline__ void flush_row(__half* __restrict__ agg,
                                          float* __restrict__ deg,
                                          int curRow, int lane,
                                          const float4& acc, float degAcc,
                                          int firstRow, bool isFinal)
{
    if (curRow < 0) return;
    __half2 h0 = __floats2half2_rn(acc.x, acc.y);
    __half2 h1 = __floats2half2_rn(acc.z, acc.w);
    __half2* p = reinterpret_cast<__half2*>(agg + (size_t)curRow * D + lane * 4);
    if (curRow == firstRow || isFinal) {
        atomicAdd(p + 0, h0);
        atomicAdd(p + 1, h1);
        if (lane == 0) atomicAdd(&deg[curRow], degAcc);
    } else {
        uint2 u = make_uint2(*reinterpret_cast<uint32_t*>(&h0),
                             *reinterpret_cast<uint32_t*>(&h1));
        *reinterpret_cast<uint2*>(p) = u;
        if (lane == 0) deg[curRow] = degAcc;
    }
}

__global__ __launch_bounds__(256) void scatter_kernel(
    const int* __restrict__ adj_row,
    const int* __restrict__ adj_col,
    const float* __restrict__ adj_val,
    const __half* __restrict__ in_h,
    __half* __restrict__ agg,
    float* __restrict__ deg,
    int E)
{
    const int warpId = (blockIdx.x * blockDim.x + threadIdx.x) >> 5;
    const int lane = threadIdx.x & 31;
    const int base = warpId * EDGES_PER_WARP;
    if (base >= E) return;

    const int firstRow = adj_row[base];
    int curRow = -1;
    float4 acc = make_float4(0.f, 0.f, 0.f, 0.f);
    float degAcc = 0.f;

    for (int t = 0; t < EDGES_PER_WARP; t += 32) {
        const int e = base + t + lane;
        int r = -2, c = 0;
        float v = 0.f;
        if (e < E) { r = adj_row[e]; c = adj_col[e]; v = adj_val[e]; }

        #pragma unroll
        for (int j = 0; j < 32; ++j) {
            const int   rj = __shfl_sync(0xFFFFFFFFu, r, j);
            const int   cj = __shfl_sync(0xFFFFFFFFu, c, j);
            const float vj = __shfl_sync(0xFFFFFFFFu, v, j);
            if (rj < 0) break;
            if (rj != curRow) {
                flush_row(agg, deg, curRow, lane, acc, degAcc, firstRow, false);
                curRow = rj;
                acc = make_float4(0.f, 0.f, 0.f, 0.f);
                degAcc = 0.f;
            }
            const uint2 sv = *reinterpret_cast<const uint2*>(
                in_h + (size_t)cj * D + lane * 4);
            const float2 f0 = __half22float2(*reinterpret_cast<const __half2*>(&sv.x));
            const float2 f1 = __half22float2(*reinterpret_cast<const __half2*>(&sv.y));
            acc.x += vj * f0.x;
            acc.y += vj * f0.y;
            acc.z += vj * f1.x;
            acc.w += vj * f1.y;
            degAcc += vj;
        }
    }
    flush_row(agg, deg, curRow, lane, acc, degAcc, firstRow, true);
}

// ===========================================================================
// mma.sync / ldmatrix / cp.async helpers
// ===========================================================================
__device__ __forceinline__ void ldmx4(uint32_t& r0, uint32_t& r1,
                                      uint32_t& r2, uint32_t& r3,
                                      uint32_t saddr)
{
    asm volatile("ldmatrix.sync.aligned.m8n8.x4.shared.b16 {%0,%1,%2,%3}, [%4];"
                 : "=r"(r0), "=r"(r1), "=r"(r2), "=r"(r3) : "r"(saddr));
}
__device__ __forceinline__ void mma_f16(float& c0, float& c1, float& c2, float& c3,
                                        uint32_t a0, uint32_t a1, uint32_t a2, uint32_t a3,
                                        uint32_t b0, uint32_t b1)
{
    asm volatile(
        "mma.sync.aligned.m16n8k16.row.col.f32.f16.f16.f32 "
        "{%0,%1,%2,%3}, {%4,%5,%6,%7}, {%8,%9}, {%0,%1,%2,%3};"
        : "+f"(c0), "+f"(c1), "+f"(c2), "+f"(c3)
        : "r"(a0), "r"(a1), "r"(a2), "r"(a3), "r"(b0), "r"(b1));
}
__device__ __forceinline__ uint32_t smem_u32(const void* p) {
    return (uint32_t)__cvta_generic_to_shared(p);
}
__device__ __forceinline__ void cp16(uint32_t dst, const void* src) {
    asm volatile("cp.async.cg.shared.global [%0], [%1], 16;" :: "r"(dst), "l"(src));
}
__device__ __forceinline__ void cp_commit() {
    asm volatile("cp.async.commit_group;");
}
template <int NWAIT>
__device__ __forceinline__ void cp_wait() {
    asm volatile("cp.async.wait_group %0;" :: "n"(NWAIT));
}

// ===========================================================================
// Kernel 2: persistent fp16 tensor-core GEMM + fused epilogue.
// Grid = ceil(nTiles/2); CTA handles tiles {bid, bid+gridDim.x}.
// W tile loaded once; second A tile prefetched (double-buffered) during
// first tile's MMA+epilogue.
// ===========================================================================
#define LDH 136                        // fp16 row stride (272 B)
#define TILE_BYTES_H (128 * LDH * 2)   // 34816 B
#define SM_BV 0
#define SM_B  1024
#define SM_A0 (SM_B + TILE_BYTES_H)
#define SM_A1 (SM_A0 + TILE_BYTES_H)
#define GEMM_SMEM_TOTAL (SM_A1 + TILE_BYTES_H)   // 105472 B

struct GemmCtx {
    const float* deg;
    float* out;
    const float* sb;
    int N, wm, wn, lane;
    uint32_t sB;
};

__device__ __forceinline__ void compute_tile(const GemmCtx& ctx, uint32_t sA,
                                             int rowBase)
{
    float acc[2][8][4];
    #pragma unroll
    for (int mi = 0; mi < 2; ++mi)
        #pragma unroll
        for (int ni = 0; ni < 8; ++ni)
            #pragma unroll
            for (int q = 0; q < 4; ++q)
                acc[mi][ni][q] = 0.f;

    const int lrow = ctx.lane & 15;
    const int lkof = (ctx.lane >> 4) << 3;

    #pragma unroll
    for (int ks = 0; ks < 8; ++ks) {
        const uint32_t kb = (uint32_t)(ks * 16 + lkof) * 2;

        uint32_t a[2][4];
        #pragma unroll
        for (int mi = 0; mi < 2; ++mi) {
            uint32_t ra = (uint32_t)((ctx.wm * 32 + mi * 16 + lrow) * LDH) * 2 + kb;
            ldmx4(a[mi][0], a[mi][1], a[mi][2], a[mi][3], sA + ra);
        }
        uint32_t bf[4][4];
        #pragma unroll
        for (int nb = 0; nb < 4; ++nb) {
            uint32_t rb = (uint32_t)((ctx.wn * 64 + nb * 16 + lrow) * LDH) * 2 + kb;
            ldmx4(bf[nb][0], bf[nb][1], bf[nb][2], bf[nb][3], ctx.sB + rb);
        }
        #pragma unroll
        for (int mi = 0; mi < 2; ++mi) {
            #pragma unroll
            for (int nb = 0; nb < 4; ++nb) {
                mma_f16(acc[mi][nb*2][0], acc[mi][nb*2][1], acc[mi][nb*2][2], acc[mi][nb*2][3],
                        a[mi][0], a[mi][1], a[mi][2], a[mi][3], bf[nb][0], bf[nb][2]);
                mma_f16(acc[mi][nb*2+1][0], acc[mi][nb*2+1][1], acc[mi][nb*2+1][2], acc[mi][nb*2+1][3],
                        a[mi][0], a[mi][1], a[mi][2], a[mi][3], bf[nb][1], bf[nb][3]);
            }
        }
    }

    const int qrow = ctx.lane >> 2;
    const int qcol = (ctx.lane & 3) << 1;

    #pragma unroll
    for (int mi = 0; mi < 2; ++mi) {
        const int r0 = rowBase + ctx.wm * 32 + mi * 16 + qrow;
        const int r1 = r0 + 8;
        const float d0 = (r0 < ctx.N) ? ctx.deg[r0] : 0.f;
        const float d1 = (r1 < ctx.N) ? ctx.deg[r1] : 0.f;
        #pragma unroll
        for (int ni = 0; ni < 8; ++ni) {
            const int c = ctx.wn * 64 + ni * 8 + qcol;
            const float b0v = ctx.sb[c], b1v = ctx.sb[c + 1];
            if (r0 < ctx.N) {
                float2 o;
                o.x = tanhf(acc[mi][ni][0] + d0 * b0v);
                o.y = tanhf(acc[mi][ni][1] + d0 * b1v);
                *reinterpret_cast<float2*>(&ctx.out[(size_t)r0 * D + c]) = o;
            }
            if (r1 < ctx.N) {
                float2 o;
                o.x = tanhf(acc[mi][ni][2] + d1 * b0v);
                o.y = tanhf(acc[mi][ni][3] + d1 * b1v);
                *reinterpret_cast<float2*>(&ctx.out[(size_t)r1 * D + c]) = o;
            }
        }
    }
}

__global__ __launch_bounds__(256, 2) void gemm_mma_kernel(
    const __half* __restrict__ agg,
    const __half* __restrict__ W_h,
    const float* __restrict__ b,
    const float* __restrict__ deg,
    float* __restrict__ out,
    int N, int nTiles)
{
    extern __shared__ char smem[];
    float* sb = reinterpret_cast<float*>(smem + SM_BV);

    const int tid  = threadIdx.x;
    const int wid  = tid >> 5;
    const int lane = tid & 31;

    const int tile0 = blockIdx.x;
    const int tile1 = blockIdx.x + gridDim.x;
    const int rowBase0 = tile0 * 128;
    const int rowBase1 = tile1 * 128;

    if (tid < 128) sb[tid] = b[tid];

    const uint32_t sB  = smem_u32(smem + SM_B);
    const uint32_t sA0 = smem_u32(smem + SM_A0);
    const uint32_t sA1 = smem_u32(smem + SM_A1);

    // Group 0: B tile + A0 tile
    #pragma unroll
    for (int it = 0; it < 8; ++it) {
        const int i = tid + it * 256;
        const int r = i >> 4;
        const int c = i & 15;
        cp16(sB  + r * (LDH * 2) + c * 16, W_h + (size_t)r * D + c * 8);
        cp16(sA0 + r * (LDH * 2) + c * 16,
             agg + (size_t)(rowBase0 + r) * D + c * 8);
    }
    cp_commit();

    // Group 1: A1 prefetch (padded agg array -> safe even if tile1 >= nTiles)
    #pragma unroll
    for (int it = 0; it < 8; ++it) {
        const int i = tid + it * 256;
        const int r = i >> 4;
        const int c = i & 15;
        cp16(sA1 + r * (LDH * 2) + c * 16,
             agg + (size_t)(rowBase1 + r) * D + c * 8);
    }
    cp_commit();

    GemmCtx ctx;
    ctx.deg = deg; ctx.out = out; ctx.sb = sb; ctx.N = N;
    ctx.wm = wid & 3; ctx.wn = wid >> 2; ctx.lane = lane; ctx.sB = sB;

    cp_wait<1>();          // group 0 complete
    __syncthreads();
    compute_tile(ctx, sA0, rowBase0);

    if (tile1 < nTiles) {
        cp_wait<0>();      // group 1 complete
        __syncthreads();
        compute_tile(ctx, sA1, rowBase1);
    }
}

// ===========================================================================
extern "C" void kernel_launch(void* const* d_in, const int* in_sizes, int n_in,
                              void* d_out, int out_size)
{
    const float* input   = (const float*)d_in[0];
    const float* W       = (const float*)d_in[1];
    const float* b       = (const float*)d_in[2];
    const int*   adj_row = (const int*)d_in[3];
    const int*   adj_col = (const int*)d_in[4];
    const float* adj_val = (const float*)d_in[5];
    float* out = (float*)d_out;

    const int N = in_sizes[0] / D;
    const int E = in_sizes[3];

    __half *inhPtr = nullptr, *whPtr = nullptr, *agghPtr = nullptr;
    float *degPtr = nullptr;
    cudaGetSymbolAddress((void**)&inhPtr, g_in_h);
    cudaGetSymbolAddress((void**)&whPtr, g_W_h);
    cudaGetSymbolAddress((void**)&agghPtr, g_agg_h);
    cudaGetSymbolAddress((void**)&degPtr, g_deg);

    // Fused prep: convert input/W to fp16 + zero agg/deg
    const int nInPairs = N * D / 8;
    const int nWPairs  = D * D / 8;
    const int nZero16  = N * D / 8;       // halves: N*D*2B / 16B
    const int nDeg4    = N / 4;
    const int totalPrep = nInPairs + nWPairs + nZero16 + nDeg4;
    prep_kernel<<<(totalPrep + 255) / 256, 256>>>(
        input, W, inhPtr, whPtr, agghPtr, degPtr,
        nInPairs, nWPairs, nZero16, nDeg4);

    // Scatter: g_agg_h = A_sparse @ input (fp16), g_deg = rowsum(adj_val)
    const int nWarps = (E + EDGES_PER_WARP - 1) / EDGES_PER_WARP;
    const int scatterBlocks = (nWarps * 32 + 255) / 256;
    scatter_kernel<<<scatterBlocks, 256>>>(adj_row, adj_col, adj_val,
                                           inhPtr, agghPtr, degPtr, E);

    // Persistent tensor-core GEMM + fused bias/tanh epilogue
    cudaFuncSetAttribute(gemm_mma_kernel,
                         cudaFuncAttributeMaxDynamicSharedMemorySize,
                         GEMM_SMEM_TOTAL);
    const int nTiles = (N + 127) / 128;
    const int gemmBlocks = (nTiles + 1) / 2;
    gemm_mma_kernel<<<gemmBlocks, 256, GEMM_SMEM_TOTAL>>>(
        agghPtr, whPtr, b, degPtr, out, N, nTiles);
}